// round 12
// baseline (speedup 1.0000x reference)
#include <cuda_runtime.h>
#include <cuda_bf16.h>
#include <math.h>
#include <stdint.h>

// ---------------------------------------------------------------------------
// Swin3D ViT block. bf16 mma.sync GEMMs (round-9 config) + head-pair
// attention blocks (full 128B-line coalesced Q/K/V loads).
// ---------------------------------------------------------------------------

#define TOK      32768
#define C_       384
#define SIXC     2304
#define NOISE_   256
#define HEADS_   12
#define NWIN     512
#define EPS_     1e-5f

// scratch
__device__ float g_params[2 * SIXC];
__device__ float g_x1[TOK * C_];
__device__ __nv_bfloat16 g_xmod[TOK * C_];
__device__ __nv_bfloat16 g_qkv[TOK * 3 * C_];
__device__ __nv_bfloat16 g_attn[TOK * C_];
__device__ __nv_bfloat16 g_h[TOK * 4 * C_];
__device__ __nv_bfloat16 g_wq[3 * C_ * C_];
__device__ __nv_bfloat16 g_wo[C_ * C_];
__device__ __nv_bfloat16 g_w1[4 * C_ * C_];
__device__ __nv_bfloat16 g_w2[4 * C_ * C_];

// ---------------------------------------------------------------------------
__device__ __forceinline__ uint32_t packbf(float lo, float hi) {
    __nv_bfloat162 t = __floats2bfloat162_rn(lo, hi);
    return *(uint32_t*)&t;
}

__device__ __forceinline__ void mmabf(float* d, const uint32_t* a, const uint32_t* b) {
    asm volatile(
        "mma.sync.aligned.m16n8k16.row.col.f32.bf16.bf16.f32 "
        "{%0,%1,%2,%3}, {%4,%5,%6,%7}, {%8,%9}, {%0,%1,%2,%3};"
        : "+f"(d[0]), "+f"(d[1]), "+f"(d[2]), "+f"(d[3])
        : "r"(a[0]), "r"(a[1]), "r"(a[2]), "r"(a[3]), "r"(b[0]), "r"(b[1]));
}

__device__ __forceinline__ void ldsm4b(uint32_t* r, uint32_t saddr) {
    asm volatile("ldmatrix.sync.aligned.m8n8.x4.shared.b16 {%0,%1,%2,%3}, [%4];"
                 : "=r"(r[0]), "=r"(r[1]), "=r"(r[2]), "=r"(r[3]) : "r"(saddr));
}

__device__ __forceinline__ void cp16b(uint32_t saddr, const void* gptr) {
    asm volatile("cp.async.cg.shared.global [%0], [%1], 16;" :: "r"(saddr), "l"(gptr));
}

// SW128-style byte swizzle within a 1KB (8-row) group of 128B rows
#define SWZB(off) ((off) ^ (((off) >> 3) & 0x70))

// ---------------------------------------------------------------------------
// merged: weight conversion (fp32->bf16) + AdaLN param GEMM in one launch
// ---------------------------------------------------------------------------
#define NWQ (3 * C_ * C_)
#define NWO (C_ * C_)
#define NW1 (4 * C_ * C_)
#define NW2 (4 * C_ * C_)
#define NCVT ((NWQ + NWO + NW1 + NW2) / 256)   // 6912 blocks

__global__ __launch_bounds__(256) void cvt_ada_kernel(
    const float* __restrict__ wq, const float* __restrict__ wo,
    const float* __restrict__ w1, const float* __restrict__ w2,
    const float* __restrict__ xn, const float* __restrict__ aw,
    const float* __restrict__ ab)
{
    if (blockIdx.x < NCVT) {
        int i = blockIdx.x * 256 + threadIdx.x;
        if (i < NWQ) { g_wq[i] = __float2bfloat16(wq[i]); return; }
        i -= NWQ;
        if (i < NWO) { g_wo[i] = __float2bfloat16(wo[i]); return; }
        i -= NWO;
        if (i < NW1) { g_w1[i] = __float2bfloat16(w1[i]); return; }
        i -= NW1;
        g_w2[i] = __float2bfloat16(w2[i]);
        return;
    }
    __shared__ float s[NOISE_];
    int bid = blockIdx.x - NCVT;
    int b  = bid / 9;
    int jb = bid % 9;
    float v = xn[b * NOISE_ + threadIdx.x];
    s[threadIdx.x] = v / (1.f + expf(-v));
    __syncthreads();
    int j = jb * 256 + threadIdx.x;
    const float* w = aw + (size_t)j * NOISE_;
    float acc = ab[j];
#pragma unroll 8
    for (int i = 0; i < NOISE_; i++) acc += w[i] * s[i];
    g_params[b * SIXC + j] = acc;
}

// ---------------------------------------------------------------------------
// LN + modulate -> bf16
// ---------------------------------------------------------------------------
__global__ __launch_bounds__(256) void ln_mod_kernel(
    const float* __restrict__ x, int shiftOff, int scaleOff,
    uint32_t* __restrict__ out)
{
    int warp = threadIdx.x >> 5, lane = threadIdx.x & 31;
    int tok = blockIdx.x * 8 + warp;
    int b = tok >> 14;
    const float4* xr = (const float4*)(x + (size_t)tok * C_);
    float4 v[3];
    float s = 0.f;
#pragma unroll
    for (int i = 0; i < 3; i++) {
        v[i] = xr[lane + 32 * i];
        s += v[i].x + v[i].y + v[i].z + v[i].w;
    }
#pragma unroll
    for (int o = 16; o; o >>= 1) s += __shfl_xor_sync(0xffffffffu, s, o);
    float mean = s * (1.f / 384.f);
    float sq = 0.f;
#pragma unroll
    for (int i = 0; i < 3; i++) {
        float dx = v[i].x - mean, dy = v[i].y - mean;
        float dz = v[i].z - mean, dw = v[i].w - mean;
        sq += dx * dx + dy * dy + dz * dz + dw * dw;
    }
#pragma unroll
    for (int o = 16; o; o >>= 1) sq += __shfl_xor_sync(0xffffffffu, sq, o);
    float rstd = rsqrtf(sq * (1.f / 384.f) + EPS_);
    const float4* sh4 = (const float4*)(g_params + b * SIXC + shiftOff);
    const float4* sc4 = (const float4*)(g_params + b * SIXC + scaleOff);
    uint32_t* orow = out + (size_t)tok * (C_ / 2);
#pragma unroll
    for (int i = 0; i < 3; i++) {
        int idx = lane + 32 * i;
        float4 s4 = sh4[idx], m4 = sc4[idx];
        float y0 = (v[i].x - mean) * rstd * (1.f + m4.x) + s4.x;
        float y1 = (v[i].y - mean) * rstd * (1.f + m4.y) + s4.y;
        float y2 = (v[i].z - mean) * rstd * (1.f + m4.z) + s4.z;
        float y3 = (v[i].w - mean) * rstd * (1.f + m4.w) + s4.w;
        orow[idx * 2]     = packbf(y0, y1);
        orow[idx * 2 + 1] = packbf(y2, y3);
    }
}

// ---------------------------------------------------------------------------
// bf16 GEMM: C[M,N] = A[M,K] @ W[N,K]^T (+bias) + epilogue. (round-9 config)
// ---------------------------------------------------------------------------
#define TILE_B   (128 * 128)
#define GEMM_SMEM (3 * 2 * TILE_B)           // 98304 bytes

template <int MODE>
__global__ __launch_bounds__(256, 2) void gemm_bf(
    const __nv_bfloat16* __restrict__ A, const __nv_bfloat16* __restrict__ Bw,
    const float* __restrict__ bias, void* __restrict__ Cout,
    int M, int N, int K,
    const float* __restrict__ res, int gateOff)
{
    extern __shared__ uint8_t smraw[];
    uint32_t sbase = (uint32_t)__cvta_generic_to_shared(smraw);

    int tid  = threadIdx.x;
    int warp = tid >> 5, lane = tid & 31;
    int g = lane >> 2, c = lane & 3;
    int wm = (warp & 1) * 64;
    int wn = (warp >> 1) * 32;
    int bm = blockIdx.y * 128;
    int bn = blockIdx.x * 128;

    int a_row = (lane & 15);
    int a_kb  = (lane >> 4) * 16;
    int b_row = (lane & 7) + ((lane >> 4) & 1) * 8;
    int b_kb  = ((lane >> 3) & 1) * 16;

    float acc[4][4][4];
#pragma unroll
    for (int i = 0; i < 4; i++)
#pragma unroll
        for (int j = 0; j < 4; j++)
#pragma unroll
            for (int t = 0; t < 4; t++) acc[i][j][t] = 0.f;

    int nk = K >> 6;

#define STAGE_LOAD(S, KT)                                                     \
    do {                                                                      \
        if ((KT) < nk) {                                                      \
            int k0 = (KT) << 6;                                               \
            uint32_t abase_ = sbase + (S) * 2 * TILE_B;                       \
            uint32_t bbase_ = abase_ + TILE_B;                                \
            _Pragma("unroll")                                                 \
            for (int i_ = 0; i_ < 4; i_++) {                                  \
                int ch_ = tid + 256 * i_;                                     \
                int row_ = ch_ >> 3, c16_ = (ch_ & 7) << 4;                   \
                uint32_t sw_ = SWZB(row_ * 128 + c16_);                       \
                cp16b(abase_ + sw_,                                           \
                      (const uint8_t*)(A + (size_t)(bm + row_) * K + k0) + c16_); \
                cp16b(bbase_ + sw_,                                           \
                      (const uint8_t*)(Bw + (size_t)(bn + row_) * K + k0) + c16_); \
            }                                                                 \
        }                                                                     \
        asm volatile("cp.async.commit_group;");                               \
    } while (0)

#define COMPUTE(S)                                                            \
    do {                                                                      \
        uint32_t abase_ = sbase + (S) * 2 * TILE_B;                           \
        uint32_t bbase_ = abase_ + TILE_B;                                    \
        _Pragma("unroll")                                                     \
        for (int kk_ = 0; kk_ < 4; kk_++) {                                   \
            int kb_ = kk_ << 5;                                               \
            uint32_t af_[4][4];                                               \
            _Pragma("unroll")                                                 \
            for (int mt_ = 0; mt_ < 4; mt_++)                                 \
                ldsm4b(af_[mt_], abase_ +                                     \
                    SWZB((wm + mt_ * 16 + a_row) * 128 + kb_ + a_kb));        \
            uint32_t bf_[2][4];                                               \
            _Pragma("unroll")                                                 \
            for (int p_ = 0; p_ < 2; p_++)                                    \
                ldsm4b(bf_[p_], bbase_ +                                      \
                    SWZB((wn + p_ * 16 + b_row) * 128 + kb_ + b_kb));         \
            _Pragma("unroll")                                                 \
            for (int mt_ = 0; mt_ < 4; mt_++)                                 \
                _Pragma("unroll")                                             \
                for (int nt_ = 0; nt_ < 4; nt_++)                             \
                    mmabf(acc[mt_][nt_], af_[mt_], &bf_[nt_ >> 1][(nt_ & 1) * 2]); \
        }                                                                     \
    } while (0)

    STAGE_LOAD(0, 0);
    STAGE_LOAD(1, 1);

    for (int kt = 0; kt < nk; kt += 3) {
        asm volatile("cp.async.wait_group 1;");
        __syncthreads();
        STAGE_LOAD(2, kt + 2);
        COMPUTE(0);

        asm volatile("cp.async.wait_group 1;");
        __syncthreads();
        STAGE_LOAD(0, kt + 3);
        COMPUTE(1);

        asm volatile("cp.async.wait_group 1;");
        __syncthreads();
        STAGE_LOAD(1, kt + 4);
        COMPUTE(2);
    }
#undef STAGE_LOAD
#undef COMPUTE

#pragma unroll
    for (int mt = 0; mt < 4; mt++) {
        int r0 = bm + wm + mt * 16 + g;
#pragma unroll
        for (int nt = 0; nt < 4; nt++) {
            int col = bn + wn + nt * 8 + (c << 1);
            float b0 = bias[col], b1 = bias[col + 1];
#pragma unroll
            for (int half = 0; half < 2; half++) {
                int row = r0 + half * 8;
                float v0 = acc[mt][nt][half * 2 + 0] + b0;
                float v1 = acc[mt][nt][half * 2 + 1] + b1;
                if (MODE == 1) {
                    v0 = 0.5f * v0 * (1.f + erff(v0 * 0.7071067811865476f));
                    v1 = 0.5f * v1 * (1.f + erff(v1 * 0.7071067811865476f));
                }
                if (MODE == 2) {
                    int bb = row >> 14;
                    float g0 = g_params[bb * SIXC + gateOff + col];
                    float g1 = g_params[bb * SIXC + gateOff + col + 1];
                    const float2 rr = *(const float2*)(res + (size_t)row * N + col);
                    *(float2*)((float*)Cout + (size_t)row * N + col) =
                        make_float2(rr.x + g0 * v0, rr.y + g1 * v1);
                } else {
                    ((uint32_t*)Cout)[(size_t)row * (N >> 1) + (col >> 1)] = packbf(v0, v1);
                }
            }
        }
    }
}

// ---------------------------------------------------------------------------
// Windowed attention, head-pair blocks. Block = (window, head-pair),
// 256 threads = 8 warps; warps 0-3 -> head 2hp, warps 4-7 -> head 2hp+1.
// Q/K/V global reads are full 128B lines per token.
// ---------------------------------------------------------------------------
__global__ __launch_bounds__(256) void attn_kernel(
    const uint32_t* __restrict__ qkv, uint32_t* __restrict__ attn_out)
{
    __shared__ uint32_t Qs[64 * 36];
    __shared__ uint32_t Ks[64 * 36];
    __shared__ __nv_bfloat16 Vt[64 * 72];

    int tid = threadIdx.x;
    int warp = tid >> 5, lane = tid & 31;
    int g = lane >> 2, c = lane & 3;
    int win = blockIdx.x / 6;
    int hp  = blockIdx.x % 6;           // head pair
    int hh  = warp >> 2;                // 0 or 1: which head of the pair
    int head = hp * 2 + hh;

    int b = win >> 8, rem = win & 255;
    int hb = rem >> 5, rem2 = rem & 31, wb = rem2 >> 2, db = rem2 & 3;
    int base = b * 16384 + hb * 4 * 512 + wb * 4 * 16 + db * 4;
    // row r -> token: base + (r>>4)*512 + ((r>>2)&3)*16 + (r&3)

    // Q,K: 64 rows x 32 u32 (both heads, 128B contiguous per row)
    for (int idx = tid; idx < 2048; idx += 256) {
        int r = idx >> 5, cc = idx & 31;
        int tok = base + (r >> 4) * 512 + ((r >> 2) & 3) * 16 + (r & 3);
        const uint32_t* p = qkv + (size_t)tok * 576 + hp * 32 + cc;
        Qs[r * 36 + cc] = p[0];
        Ks[r * 36 + cc] = p[192];
    }
    // V transposed: Vt[e][key], e = hd within pair (0..63)
    const __nv_bfloat16* qkvh = (const __nv_bfloat16*)qkv;
    for (int idx = tid; idx < 4096; idx += 256) {
        int r = idx >> 6, e = idx & 63;
        int tok = base + (r >> 4) * 512 + ((r >> 2) & 3) * 16 + (r & 3);
        Vt[e * 72 + r] = qkvh[(size_t)tok * 1152 + 768 + hp * 64 + e];
    }
    __syncthreads();

    int ho = hh * 16;                   // u32 col offset for this head in Qs/Ks
    int r0 = (warp & 3) * 16;

    float sacc[8][4];
#pragma unroll
    for (int i = 0; i < 8; i++)
#pragma unroll
        for (int t = 0; t < 4; t++) sacc[i][t] = 0.f;

#pragma unroll
    for (int ks = 0; ks < 2; ks++) {
        int kb = ks << 3;
        uint32_t af[4];
        af[0] = Qs[(r0 + g) * 36 + ho + kb + c];
        af[1] = Qs[(r0 + g + 8) * 36 + ho + kb + c];
        af[2] = Qs[(r0 + g) * 36 + ho + kb + c + 4];
        af[3] = Qs[(r0 + g + 8) * 36 + ho + kb + c + 4];
#pragma unroll
        for (int nt = 0; nt < 8; nt++) {
            uint32_t bfr[2];
            bfr[0] = Ks[(nt * 8 + g) * 36 + ho + kb + c];
            bfr[1] = Ks[(nt * 8 + g) * 36 + ho + kb + c + 4];
            mmabf(sacc[nt], af, bfr);
        }
    }

    const float SC = 0.17677669529663687f;
    float slo = 0.f, shi = 0.f;
#pragma unroll
    for (int nt = 0; nt < 8; nt++) {
        sacc[nt][0] = __expf(sacc[nt][0] * SC);
        sacc[nt][1] = __expf(sacc[nt][1] * SC);
        sacc[nt][2] = __expf(sacc[nt][2] * SC);
        sacc[nt][3] = __expf(sacc[nt][3] * SC);
        slo += sacc[nt][0] + sacc[nt][1];
        shi += sacc[nt][2] + sacc[nt][3];
    }
    slo += __shfl_xor_sync(0xffffffffu, slo, 1);
    slo += __shfl_xor_sync(0xffffffffu, slo, 2);
    shi += __shfl_xor_sync(0xffffffffu, shi, 1);
    shi += __shfl_xor_sync(0xffffffffu, shi, 2);

    float o[4][4];
#pragma unroll
    for (int i = 0; i < 4; i++)
#pragma unroll
        for (int t = 0; t < 4; t++) o[i][t] = 0.f;

    const uint32_t* Vt32 = (const uint32_t*)Vt;
    int vo = hh * 32;                   // Vt row offset for this head
#pragma unroll
    for (int kt = 0; kt < 4; kt++) {
        uint32_t pa[4];
        pa[0] = packbf(sacc[2 * kt][0],     sacc[2 * kt][1]);
        pa[1] = packbf(sacc[2 * kt][2],     sacc[2 * kt][3]);
        pa[2] = packbf(sacc[2 * kt + 1][0], sacc[2 * kt + 1][1]);
        pa[3] = packbf(sacc[2 * kt + 1][2], sacc[2 * kt + 1][3]);
#pragma unroll
        for (int nt = 0; nt < 4; nt++) {
            uint32_t bfr[2];
            const uint32_t* vrow = Vt32 + (vo + nt * 8 + g) * 36;
            bfr[0] = vrow[kt * 8 + c];
            bfr[1] = vrow[kt * 8 + c + 4];
            mmabf(o[nt], pa, bfr);
        }
    }

    float inv_lo = 1.f / slo, inv_hi = 1.f / shi;
#pragma unroll
    for (int half = 0; half < 2; half++) {
        int r = r0 + g + half * 8;
        int tok = base + (r >> 4) * 512 + ((r >> 2) & 3) * 16 + (r & 3);
        uint32_t* op = attn_out + (size_t)tok * 192 + head * 16;
        float inv = half ? inv_hi : inv_lo;
#pragma unroll
        for (int nt = 0; nt < 4; nt++)
            op[nt * 4 + c] = packbf(o[nt][half * 2] * inv, o[nt][half * 2 + 1] * inv);
    }
}

// ---------------------------------------------------------------------------
// launch
// ---------------------------------------------------------------------------
extern "C" void kernel_launch(void* const* d_in, const int* in_sizes, int n_in,
                              void* d_out, int out_size)
{
    const float* x      = (const float*)d_in[0];
    const float* xn     = (const float*)d_in[1];
    const float* ada_w  = (const float*)d_in[2];
    const float* ada_b  = (const float*)d_in[3];
    const float* qkv_w  = (const float*)d_in[4];
    const float* qkv_b  = (const float*)d_in[5];
    const float* out_w  = (const float*)d_in[6];
    const float* out_b  = (const float*)d_in[7];
    const float* mlp_w1 = (const float*)d_in[8];
    const float* mlp_b1 = (const float*)d_in[9];
    const float* mlp_w2 = (const float*)d_in[10];
    const float* mlp_b2 = (const float*)d_in[11];
    float* out = (float*)d_out;

    void *p_xmod, *p_qkv, *p_attn, *p_x1, *p_h, *p_wq, *p_wo, *p_w1, *p_w2;
    cudaGetSymbolAddress(&p_xmod, g_xmod);
    cudaGetSymbolAddress(&p_qkv,  g_qkv);
    cudaGetSymbolAddress(&p_attn, g_attn);
    cudaGetSymbolAddress(&p_x1,   g_x1);
    cudaGetSymbolAddress(&p_h,    g_h);
    cudaGetSymbolAddress(&p_wq,   g_wq);
    cudaGetSymbolAddress(&p_wo,   g_wo);
    cudaGetSymbolAddress(&p_w1,   g_w1);
    cudaGetSymbolAddress(&p_w2,   g_w2);

    cudaFuncSetAttribute(gemm_bf<0>, cudaFuncAttributeMaxDynamicSharedMemorySize, GEMM_SMEM);
    cudaFuncSetAttribute(gemm_bf<1>, cudaFuncAttributeMaxDynamicSharedMemorySize, GEMM_SMEM);
    cudaFuncSetAttribute(gemm_bf<2>, cudaFuncAttributeMaxDynamicSharedMemorySize, GEMM_SMEM);

    cvt_ada_kernel<<<NCVT + 18, 256>>>(qkv_w, out_w, mlp_w1, mlp_w2,
                                       xn, ada_w, ada_b);

    ln_mod_kernel<<<TOK / 8, 256>>>(x, 0, C_, (uint32_t*)p_xmod);

    {   // QKV -> bf16 (nk=6)
        dim3 grid((3 * C_) / 128, TOK / 128);
        gemm_bf<0><<<grid, 256, GEMM_SMEM>>>(
            (const __nv_bfloat16*)p_xmod, (const __nv_bfloat16*)p_wq,
            qkv_b, p_qkv, TOK, 3 * C_, C_, nullptr, 0);
    }

    attn_kernel<<<NWIN * 6, 256>>>((const uint32_t*)p_qkv, (uint32_t*)p_attn);

    {   // out proj + gate1 + residual -> fp32 (nk=6)
        dim3 grid(C_ / 128, TOK / 128);
        gemm_bf<2><<<grid, 256, GEMM_SMEM>>>(
            (const __nv_bfloat16*)p_attn, (const __nv_bfloat16*)p_wo,
            out_b, p_x1, TOK, C_, C_, x, 2 * C_);
    }

    ln_mod_kernel<<<TOK / 8, 256>>>((const float*)p_x1, 3 * C_, 4 * C_, (uint32_t*)p_xmod);

    {   // MLP1 + GELU -> bf16 (nk=6)
        dim3 grid((4 * C_) / 128, TOK / 128);
        gemm_bf<1><<<grid, 256, GEMM_SMEM>>>(
            (const __nv_bfloat16*)p_xmod, (const __nv_bfloat16*)p_w1,
            mlp_b1, p_h, TOK, 4 * C_, C_, nullptr, 0);
    }

    {   // MLP2 + gate2 + residual -> fp32 (nk=24)
        dim3 grid(C_ / 128, TOK / 128);
        gemm_bf<2><<<grid, 256, GEMM_SMEM>>>(
            (const __nv_bfloat16*)p_h, (const __nv_bfloat16*)p_w2,
            mlp_b2, out, TOK, C_, 4 * C_, (const float*)p_x1, 5 * C_);
    }
}

// round 13
// speedup vs baseline: 1.0568x; 1.0568x over previous
#include <cuda_runtime.h>
#include <cuda_bf16.h>
#include <math.h>
#include <stdint.h>

// ---------------------------------------------------------------------------
// Swin3D ViT block. bf16 mma.sync GEMMs (round-9 config, 557us baseline) +
// attention rewritten with ldmatrix fragments (incl. x4.trans for V).
// ---------------------------------------------------------------------------

#define TOK      32768
#define C_       384
#define SIXC     2304
#define NOISE_   256
#define HEADS_   12
#define NWIN     512
#define EPS_     1e-5f

// scratch
__device__ float g_params[2 * SIXC];
__device__ float g_x1[TOK * C_];
__device__ __nv_bfloat16 g_xmod[TOK * C_];
__device__ __nv_bfloat16 g_qkv[TOK * 3 * C_];
__device__ __nv_bfloat16 g_attn[TOK * C_];
__device__ __nv_bfloat16 g_h[TOK * 4 * C_];
__device__ __nv_bfloat16 g_wq[3 * C_ * C_];
__device__ __nv_bfloat16 g_wo[C_ * C_];
__device__ __nv_bfloat16 g_w1[4 * C_ * C_];
__device__ __nv_bfloat16 g_w2[4 * C_ * C_];

// ---------------------------------------------------------------------------
__device__ __forceinline__ uint32_t packbf(float lo, float hi) {
    __nv_bfloat162 t = __floats2bfloat162_rn(lo, hi);
    return *(uint32_t*)&t;
}

__device__ __forceinline__ void mmabf(float* d, const uint32_t* a, const uint32_t* b) {
    asm volatile(
        "mma.sync.aligned.m16n8k16.row.col.f32.bf16.bf16.f32 "
        "{%0,%1,%2,%3}, {%4,%5,%6,%7}, {%8,%9}, {%0,%1,%2,%3};"
        : "+f"(d[0]), "+f"(d[1]), "+f"(d[2]), "+f"(d[3])
        : "r"(a[0]), "r"(a[1]), "r"(a[2]), "r"(a[3]), "r"(b[0]), "r"(b[1]));
}

__device__ __forceinline__ void ldsm4b(uint32_t* r, uint32_t saddr) {
    asm volatile("ldmatrix.sync.aligned.m8n8.x4.shared.b16 {%0,%1,%2,%3}, [%4];"
                 : "=r"(r[0]), "=r"(r[1]), "=r"(r[2]), "=r"(r[3]) : "r"(saddr));
}

__device__ __forceinline__ void ldsm4t(uint32_t* r, uint32_t saddr) {
    asm volatile("ldmatrix.sync.aligned.m8n8.x4.trans.shared.b16 {%0,%1,%2,%3}, [%4];"
                 : "=r"(r[0]), "=r"(r[1]), "=r"(r[2]), "=r"(r[3]) : "r"(saddr));
}

__device__ __forceinline__ void cp16b(uint32_t saddr, const void* gptr) {
    asm volatile("cp.async.cg.shared.global [%0], [%1], 16;" :: "r"(saddr), "l"(gptr));
}

#define SWZB(off) ((off) ^ (((off) >> 3) & 0x70))

// ---------------------------------------------------------------------------
// merged: weight conversion (fp32->bf16) + AdaLN param GEMM in one launch
// ---------------------------------------------------------------------------
#define NWQ (3 * C_ * C_)
#define NWO (C_ * C_)
#define NW1 (4 * C_ * C_)
#define NW2 (4 * C_ * C_)
#define NCVT ((NWQ + NWO + NW1 + NW2) / 256)

__global__ __launch_bounds__(256) void cvt_ada_kernel(
    const float* __restrict__ wq, const float* __restrict__ wo,
    const float* __restrict__ w1, const float* __restrict__ w2,
    const float* __restrict__ xn, const float* __restrict__ aw,
    const float* __restrict__ ab)
{
    if (blockIdx.x < NCVT) {
        int i = blockIdx.x * 256 + threadIdx.x;
        if (i < NWQ) { g_wq[i] = __float2bfloat16(wq[i]); return; }
        i -= NWQ;
        if (i < NWO) { g_wo[i] = __float2bfloat16(wo[i]); return; }
        i -= NWO;
        if (i < NW1) { g_w1[i] = __float2bfloat16(w1[i]); return; }
        i -= NW1;
        g_w2[i] = __float2bfloat16(w2[i]);
        return;
    }
    __shared__ float s[NOISE_];
    int bid = blockIdx.x - NCVT;
    int b  = bid / 9;
    int jb = bid % 9;
    float v = xn[b * NOISE_ + threadIdx.x];
    s[threadIdx.x] = v / (1.f + expf(-v));
    __syncthreads();
    int j = jb * 256 + threadIdx.x;
    const float* w = aw + (size_t)j * NOISE_;
    float acc = ab[j];
#pragma unroll 8
    for (int i = 0; i < NOISE_; i++) acc += w[i] * s[i];
    g_params[b * SIXC + j] = acc;
}

// ---------------------------------------------------------------------------
// LN + modulate -> bf16
// ---------------------------------------------------------------------------
__global__ __launch_bounds__(256) void ln_mod_kernel(
    const float* __restrict__ x, int shiftOff, int scaleOff,
    uint32_t* __restrict__ out)
{
    int warp = threadIdx.x >> 5, lane = threadIdx.x & 31;
    int tok = blockIdx.x * 8 + warp;
    int b = tok >> 14;
    const float4* xr = (const float4*)(x + (size_t)tok * C_);
    float4 v[3];
    float s = 0.f;
#pragma unroll
    for (int i = 0; i < 3; i++) {
        v[i] = xr[lane + 32 * i];
        s += v[i].x + v[i].y + v[i].z + v[i].w;
    }
#pragma unroll
    for (int o = 16; o; o >>= 1) s += __shfl_xor_sync(0xffffffffu, s, o);
    float mean = s * (1.f / 384.f);
    float sq = 0.f;
#pragma unroll
    for (int i = 0; i < 3; i++) {
        float dx = v[i].x - mean, dy = v[i].y - mean;
        float dz = v[i].z - mean, dw = v[i].w - mean;
        sq += dx * dx + dy * dy + dz * dz + dw * dw;
    }
#pragma unroll
    for (int o = 16; o; o >>= 1) sq += __shfl_xor_sync(0xffffffffu, sq, o);
    float rstd = rsqrtf(sq * (1.f / 384.f) + EPS_);
    const float4* sh4 = (const float4*)(g_params + b * SIXC + shiftOff);
    const float4* sc4 = (const float4*)(g_params + b * SIXC + scaleOff);
    uint32_t* orow = out + (size_t)tok * (C_ / 2);
#pragma unroll
    for (int i = 0; i < 3; i++) {
        int idx = lane + 32 * i;
        float4 s4 = sh4[idx], m4 = sc4[idx];
        float y0 = (v[i].x - mean) * rstd * (1.f + m4.x) + s4.x;
        float y1 = (v[i].y - mean) * rstd * (1.f + m4.y) + s4.y;
        float y2 = (v[i].z - mean) * rstd * (1.f + m4.z) + s4.z;
        float y3 = (v[i].w - mean) * rstd * (1.f + m4.w) + s4.w;
        orow[idx * 2]     = packbf(y0, y1);
        orow[idx * 2 + 1] = packbf(y2, y3);
    }
}

// ---------------------------------------------------------------------------
// bf16 GEMM: (round-9 config, unchanged)
// ---------------------------------------------------------------------------
#define TILE_B   (128 * 128)
#define GEMM_SMEM (3 * 2 * TILE_B)

template <int MODE>
__global__ __launch_bounds__(256, 2) void gemm_bf(
    const __nv_bfloat16* __restrict__ A, const __nv_bfloat16* __restrict__ Bw,
    const float* __restrict__ bias, void* __restrict__ Cout,
    int M, int N, int K,
    const float* __restrict__ res, int gateOff)
{
    extern __shared__ uint8_t smraw[];
    uint32_t sbase = (uint32_t)__cvta_generic_to_shared(smraw);

    int tid  = threadIdx.x;
    int warp = tid >> 5, lane = tid & 31;
    int g = lane >> 2, c = lane & 3;
    int wm = (warp & 1) * 64;
    int wn = (warp >> 1) * 32;
    int bm = blockIdx.y * 128;
    int bn = blockIdx.x * 128;

    int a_row = (lane & 15);
    int a_kb  = (lane >> 4) * 16;
    int b_row = (lane & 7) + ((lane >> 4) & 1) * 8;
    int b_kb  = ((lane >> 3) & 1) * 16;

    float acc[4][4][4];
#pragma unroll
    for (int i = 0; i < 4; i++)
#pragma unroll
        for (int j = 0; j < 4; j++)
#pragma unroll
            for (int t = 0; t < 4; t++) acc[i][j][t] = 0.f;

    int nk = K >> 6;

#define STAGE_LOAD(S, KT)                                                     \
    do {                                                                      \
        if ((KT) < nk) {                                                      \
            int k0 = (KT) << 6;                                               \
            uint32_t abase_ = sbase + (S) * 2 * TILE_B;                       \
            uint32_t bbase_ = abase_ + TILE_B;                                \
            _Pragma("unroll")                                                 \
            for (int i_ = 0; i_ < 4; i_++) {                                  \
                int ch_ = tid + 256 * i_;                                     \
                int row_ = ch_ >> 3, c16_ = (ch_ & 7) << 4;                   \
                uint32_t sw_ = SWZB(row_ * 128 + c16_);                       \
                cp16b(abase_ + sw_,                                           \
                      (const uint8_t*)(A + (size_t)(bm + row_) * K + k0) + c16_); \
                cp16b(bbase_ + sw_,                                           \
                      (const uint8_t*)(Bw + (size_t)(bn + row_) * K + k0) + c16_); \
            }                                                                 \
        }                                                                     \
        asm volatile("cp.async.commit_group;");                               \
    } while (0)

#define COMPUTE(S)                                                            \
    do {                                                                      \
        uint32_t abase_ = sbase + (S) * 2 * TILE_B;                           \
        uint32_t bbase_ = abase_ + TILE_B;                                    \
        _Pragma("unroll")                                                     \
        for (int kk_ = 0; kk_ < 4; kk_++) {                                   \
            int kb_ = kk_ << 5;                                               \
            uint32_t af_[4][4];                                               \
            _Pragma("unroll")                                                 \
            for (int mt_ = 0; mt_ < 4; mt_++)                                 \
                ldsm4b(af_[mt_], abase_ +                                     \
                    SWZB((wm + mt_ * 16 + a_row) * 128 + kb_ + a_kb));        \
            uint32_t bf_[2][4];                                               \
            _Pragma("unroll")                                                 \
            for (int p_ = 0; p_ < 2; p_++)                                    \
                ldsm4b(bf_[p_], bbase_ +                                      \
                    SWZB((wn + p_ * 16 + b_row) * 128 + kb_ + b_kb));         \
            _Pragma("unroll")                                                 \
            for (int mt_ = 0; mt_ < 4; mt_++)                                 \
                _Pragma("unroll")                                             \
                for (int nt_ = 0; nt_ < 4; nt_++)                             \
                    mmabf(acc[mt_][nt_], af_[mt_], &bf_[nt_ >> 1][(nt_ & 1) * 2]); \
        }                                                                     \
    } while (0)

    STAGE_LOAD(0, 0);
    STAGE_LOAD(1, 1);

    for (int kt = 0; kt < nk; kt += 3) {
        asm volatile("cp.async.wait_group 1;");
        __syncthreads();
        STAGE_LOAD(2, kt + 2);
        COMPUTE(0);

        asm volatile("cp.async.wait_group 1;");
        __syncthreads();
        STAGE_LOAD(0, kt + 3);
        COMPUTE(1);

        asm volatile("cp.async.wait_group 1;");
        __syncthreads();
        STAGE_LOAD(1, kt + 4);
        COMPUTE(2);
    }
#undef STAGE_LOAD
#undef COMPUTE

#pragma unroll
    for (int mt = 0; mt < 4; mt++) {
        int r0 = bm + wm + mt * 16 + g;
#pragma unroll
        for (int nt = 0; nt < 4; nt++) {
            int col = bn + wn + nt * 8 + (c << 1);
            float b0 = bias[col], b1 = bias[col + 1];
#pragma unroll
            for (int half = 0; half < 2; half++) {
                int row = r0 + half * 8;
                float v0 = acc[mt][nt][half * 2 + 0] + b0;
                float v1 = acc[mt][nt][half * 2 + 1] + b1;
                if (MODE == 1) {
                    v0 = 0.5f * v0 * (1.f + erff(v0 * 0.7071067811865476f));
                    v1 = 0.5f * v1 * (1.f + erff(v1 * 0.7071067811865476f));
                }
                if (MODE == 2) {
                    int bb = row >> 14;
                    float g0 = g_params[bb * SIXC + gateOff + col];
                    float g1 = g_params[bb * SIXC + gateOff + col + 1];
                    const float2 rr = *(const float2*)(res + (size_t)row * N + col);
                    *(float2*)((float*)Cout + (size_t)row * N + col) =
                        make_float2(rr.x + g0 * v0, rr.y + g1 * v1);
                } else {
                    ((uint32_t*)Cout)[(size_t)row * (N >> 1) + (col >> 1)] = packbf(v0, v1);
                }
            }
        }
    }
}

// ---------------------------------------------------------------------------
// Windowed attention, bf16 mma.sync + ldmatrix (x4 / x4.trans for V).
// Block = (window, head), 128 threads = 4 warps.
// ---------------------------------------------------------------------------
__global__ __launch_bounds__(128) void attn_kernel(
    const uint32_t* __restrict__ qkv, uint32_t* __restrict__ attn_out)
{
    __shared__ uint32_t Qs[64 * 20];
    __shared__ uint32_t Ks[64 * 20];
    __shared__ uint32_t Vs[64 * 20];

    int tid = threadIdx.x;
    int warp = tid >> 5, lane = tid & 31;
    int g = lane >> 2, c = lane & 3;
    int win  = blockIdx.x / HEADS_;
    int head = blockIdx.x % HEADS_;

    int b = win >> 8, rem = win & 255;
    int hb = rem >> 5, rem2 = rem & 31, wb = rem2 >> 2, db = rem2 & 3;
    int base = b * 16384 + hb * 4 * 512 + wb * 4 * 16 + db * 4;

    // stage Q, K, V (all coalesced u32 rows, stride-20)
    for (int idx = tid; idx < 1024; idx += 128) {
        int r = idx >> 4, cc = idx & 15;
        int tok = base + (r >> 4) * 512 + ((r >> 2) & 3) * 16 + (r & 3);
        const uint32_t* p = qkv + (size_t)tok * 576 + head * 16 + cc;
        Qs[r * 20 + cc] = p[0];
        Ks[r * 20 + cc] = p[192];
        Vs[r * 20 + cc] = p[384];
    }
    __syncthreads();

    uint32_t qb = (uint32_t)__cvta_generic_to_shared(Qs);
    uint32_t kb_a = (uint32_t)__cvta_generic_to_shared(Ks);
    uint32_t vb = (uint32_t)__cvta_generic_to_shared(Vs);

    int r0 = warp * 16;
    // ldsm lane mappings (u32 column units; *4 for bytes)
    int a_row = lane & 15;
    int a_ko  = (lane >> 4) * 4;
    int b_row = (lane & 7) + ((lane >> 4) & 1) * 8;
    int b_ko  = ((lane >> 3) & 1) * 4;
    int v_row = ((lane >> 3) & 1) * 8 + (lane & 7);
    int v_co  = (lane >> 4) * 4;

    // S = Q @ K^T
    float sacc[8][4];
#pragma unroll
    for (int i = 0; i < 8; i++)
#pragma unroll
        for (int t = 0; t < 4; t++) sacc[i][t] = 0.f;

#pragma unroll
    for (int ks = 0; ks < 2; ks++) {
        int kbo = ks << 3;
        uint32_t af[4];
        ldsm4b(af, qb + ((r0 + a_row) * 20 + kbo + a_ko) * 4);
#pragma unroll
        for (int p = 0; p < 4; p++) {
            uint32_t bfr[4];
            ldsm4b(bfr, kb_a + ((p * 16 + b_row) * 20 + kbo + b_ko) * 4);
            mmabf(sacc[p * 2],     af, &bfr[0]);
            mmabf(sacc[p * 2 + 1], af, &bfr[2]);
        }
    }

    // softmax (no max-pass; scores O(1)); exp2 with folded log2(e)
    const float SC2 = 0.17677669529663687f * 1.4426950408889634f;
    float slo = 0.f, shi = 0.f;
#pragma unroll
    for (int nt = 0; nt < 8; nt++) {
        sacc[nt][0] = exp2f(sacc[nt][0] * SC2);
        sacc[nt][1] = exp2f(sacc[nt][1] * SC2);
        sacc[nt][2] = exp2f(sacc[nt][2] * SC2);
        sacc[nt][3] = exp2f(sacc[nt][3] * SC2);
        slo += sacc[nt][0] + sacc[nt][1];
        shi += sacc[nt][2] + sacc[nt][3];
    }
    slo += __shfl_xor_sync(0xffffffffu, slo, 1);
    slo += __shfl_xor_sync(0xffffffffu, slo, 2);
    shi += __shfl_xor_sync(0xffffffffu, shi, 1);
    shi += __shfl_xor_sync(0xffffffffu, shi, 2);

    // O = P @ V  (V fragments via ldmatrix.trans on coalesced [key][hd] rows)
    float o[4][4];
#pragma unroll
    for (int i = 0; i < 4; i++)
#pragma unroll
        for (int t = 0; t < 4; t++) o[i][t] = 0.f;

#pragma unroll
    for (int kt = 0; kt < 4; kt++) {
        uint32_t pa[4];
        pa[0] = packbf(sacc[2 * kt][0],     sacc[2 * kt][1]);
        pa[1] = packbf(sacc[2 * kt][2],     sacc[2 * kt][3]);
        pa[2] = packbf(sacc[2 * kt + 1][0], sacc[2 * kt + 1][1]);
        pa[3] = packbf(sacc[2 * kt + 1][2], sacc[2 * kt + 1][3]);
#pragma unroll
        for (int vt = 0; vt < 2; vt++) {
            uint32_t vf[4];
            ldsm4t(vf, vb + ((kt * 16 + v_row) * 20 + vt * 8 + v_co) * 4);
            mmabf(o[vt * 2],     pa, &vf[0]);
            mmabf(o[vt * 2 + 1], pa, &vf[2]);
        }
    }

    float inv_lo = 1.f / slo, inv_hi = 1.f / shi;
#pragma unroll
    for (int half = 0; half < 2; half++) {
        int r = r0 + g + half * 8;
        int tok = base + (r >> 4) * 512 + ((r >> 2) & 3) * 16 + (r & 3);
        uint32_t* op = attn_out + (size_t)tok * 192 + head * 16;
        float inv = half ? inv_hi : inv_lo;
#pragma unroll
        for (int nt = 0; nt < 4; nt++)
            op[nt * 4 + c] = packbf(o[nt][half * 2] * inv, o[nt][half * 2 + 1] * inv);
    }
}

// ---------------------------------------------------------------------------
// launch
// ---------------------------------------------------------------------------
extern "C" void kernel_launch(void* const* d_in, const int* in_sizes, int n_in,
                              void* d_out, int out_size)
{
    const float* x      = (const float*)d_in[0];
    const float* xn     = (const float*)d_in[1];
    const float* ada_w  = (const float*)d_in[2];
    const float* ada_b  = (const float*)d_in[3];
    const float* qkv_w  = (const float*)d_in[4];
    const float* qkv_b  = (const float*)d_in[5];
    const float* out_w  = (const float*)d_in[6];
    const float* out_b  = (const float*)d_in[7];
    const float* mlp_w1 = (const float*)d_in[8];
    const float* mlp_b1 = (const float*)d_in[9];
    const float* mlp_w2 = (const float*)d_in[10];
    const float* mlp_b2 = (const float*)d_in[11];
    float* out = (float*)d_out;

    void *p_xmod, *p_qkv, *p_attn, *p_x1, *p_h, *p_wq, *p_wo, *p_w1, *p_w2;
    cudaGetSymbolAddress(&p_xmod, g_xmod);
    cudaGetSymbolAddress(&p_qkv,  g_qkv);
    cudaGetSymbolAddress(&p_attn, g_attn);
    cudaGetSymbolAddress(&p_x1,   g_x1);
    cudaGetSymbolAddress(&p_h,    g_h);
    cudaGetSymbolAddress(&p_wq,   g_wq);
    cudaGetSymbolAddress(&p_wo,   g_wo);
    cudaGetSymbolAddress(&p_w1,   g_w1);
    cudaGetSymbolAddress(&p_w2,   g_w2);

    cudaFuncSetAttribute(gemm_bf<0>, cudaFuncAttributeMaxDynamicSharedMemorySize, GEMM_SMEM);
    cudaFuncSetAttribute(gemm_bf<1>, cudaFuncAttributeMaxDynamicSharedMemorySize, GEMM_SMEM);
    cudaFuncSetAttribute(gemm_bf<2>, cudaFuncAttributeMaxDynamicSharedMemorySize, GEMM_SMEM);

    cvt_ada_kernel<<<NCVT + 18, 256>>>(qkv_w, out_w, mlp_w1, mlp_w2,
                                       xn, ada_w, ada_b);

    ln_mod_kernel<<<TOK / 8, 256>>>(x, 0, C_, (uint32_t*)p_xmod);

    {   // QKV -> bf16 (nk=6)
        dim3 grid((3 * C_) / 128, TOK / 128);
        gemm_bf<0><<<grid, 256, GEMM_SMEM>>>(
            (const __nv_bfloat16*)p_xmod, (const __nv_bfloat16*)p_wq,
            qkv_b, p_qkv, TOK, 3 * C_, C_, nullptr, 0);
    }

    attn_kernel<<<NWIN * HEADS_, 128>>>((const uint32_t*)p_qkv, (uint32_t*)p_attn);

    {   // out proj + gate1 + residual -> fp32 (nk=6)
        dim3 grid(C_ / 128, TOK / 128);
        gemm_bf<2><<<grid, 256, GEMM_SMEM>>>(
            (const __nv_bfloat16*)p_attn, (const __nv_bfloat16*)p_wo,
            out_b, p_x1, TOK, C_, C_, x, 2 * C_);
    }

    ln_mod_kernel<<<TOK / 8, 256>>>((const float*)p_x1, 3 * C_, 4 * C_, (uint32_t*)p_xmod);

    {   // MLP1 + GELU -> bf16 (nk=6)
        dim3 grid((4 * C_) / 128, TOK / 128);
        gemm_bf<1><<<grid, 256, GEMM_SMEM>>>(
            (const __nv_bfloat16*)p_xmod, (const __nv_bfloat16*)p_w1,
            mlp_b1, p_h, TOK, 4 * C_, C_, nullptr, 0);
    }

    {   // MLP2 + gate2 + residual -> fp32 (nk=24)
        dim3 grid(C_ / 128, TOK / 128);
        gemm_bf<2><<<grid, 256, GEMM_SMEM>>>(
            (const __nv_bfloat16*)p_h, (const __nv_bfloat16*)p_w2,
            mlp_b2, out, TOK, C_, 4 * C_, (const float*)p_x1, 5 * C_);
    }
}

// round 14
// speedup vs baseline: 1.0874x; 1.0290x over previous
#include <cuda_runtime.h>
#include <cuda_bf16.h>
#include <math.h>
#include <stdint.h>

// ---------------------------------------------------------------------------
// Swin3D ViT block. bf16 mma.sync GEMMs (round-9 config) + ldmatrix attention
// with cp.async staging.
// ---------------------------------------------------------------------------

#define TOK      32768
#define C_       384
#define SIXC     2304
#define NOISE_   256
#define HEADS_   12
#define NWIN     512
#define EPS_     1e-5f

// scratch
__device__ float g_params[2 * SIXC];
__device__ float g_x1[TOK * C_];
__device__ __nv_bfloat16 g_xmod[TOK * C_];
__device__ __nv_bfloat16 g_qkv[TOK * 3 * C_];
__device__ __nv_bfloat16 g_attn[TOK * C_];
__device__ __nv_bfloat16 g_h[TOK * 4 * C_];
__device__ __nv_bfloat16 g_wq[3 * C_ * C_];
__device__ __nv_bfloat16 g_wo[C_ * C_];
__device__ __nv_bfloat16 g_w1[4 * C_ * C_];
__device__ __nv_bfloat16 g_w2[4 * C_ * C_];

// ---------------------------------------------------------------------------
__device__ __forceinline__ uint32_t packbf(float lo, float hi) {
    __nv_bfloat162 t = __floats2bfloat162_rn(lo, hi);
    return *(uint32_t*)&t;
}

__device__ __forceinline__ void mmabf(float* d, const uint32_t* a, const uint32_t* b) {
    asm volatile(
        "mma.sync.aligned.m16n8k16.row.col.f32.bf16.bf16.f32 "
        "{%0,%1,%2,%3}, {%4,%5,%6,%7}, {%8,%9}, {%0,%1,%2,%3};"
        : "+f"(d[0]), "+f"(d[1]), "+f"(d[2]), "+f"(d[3])
        : "r"(a[0]), "r"(a[1]), "r"(a[2]), "r"(a[3]), "r"(b[0]), "r"(b[1]));
}

__device__ __forceinline__ void ldsm4b(uint32_t* r, uint32_t saddr) {
    asm volatile("ldmatrix.sync.aligned.m8n8.x4.shared.b16 {%0,%1,%2,%3}, [%4];"
                 : "=r"(r[0]), "=r"(r[1]), "=r"(r[2]), "=r"(r[3]) : "r"(saddr));
}

__device__ __forceinline__ void ldsm4t(uint32_t* r, uint32_t saddr) {
    asm volatile("ldmatrix.sync.aligned.m8n8.x4.trans.shared.b16 {%0,%1,%2,%3}, [%4];"
                 : "=r"(r[0]), "=r"(r[1]), "=r"(r[2]), "=r"(r[3]) : "r"(saddr));
}

__device__ __forceinline__ void cp16b(uint32_t saddr, const void* gptr) {
    asm volatile("cp.async.cg.shared.global [%0], [%1], 16;" :: "r"(saddr), "l"(gptr));
}

#define SWZB(off) ((off) ^ (((off) >> 3) & 0x70))

// ---------------------------------------------------------------------------
// merged: weight conversion + AdaLN param GEMM
// ---------------------------------------------------------------------------
#define NWQ (3 * C_ * C_)
#define NWO (C_ * C_)
#define NW1 (4 * C_ * C_)
#define NW2 (4 * C_ * C_)
#define NCVT ((NWQ + NWO + NW1 + NW2) / 256)

__global__ __launch_bounds__(256) void cvt_ada_kernel(
    const float* __restrict__ wq, const float* __restrict__ wo,
    const float* __restrict__ w1, const float* __restrict__ w2,
    const float* __restrict__ xn, const float* __restrict__ aw,
    const float* __restrict__ ab)
{
    if (blockIdx.x < NCVT) {
        int i = blockIdx.x * 256 + threadIdx.x;
        if (i < NWQ) { g_wq[i] = __float2bfloat16(wq[i]); return; }
        i -= NWQ;
        if (i < NWO) { g_wo[i] = __float2bfloat16(wo[i]); return; }
        i -= NWO;
        if (i < NW1) { g_w1[i] = __float2bfloat16(w1[i]); return; }
        i -= NW1;
        g_w2[i] = __float2bfloat16(w2[i]);
        return;
    }
    __shared__ float s[NOISE_];
    int bid = blockIdx.x - NCVT;
    int b  = bid / 9;
    int jb = bid % 9;
    float v = xn[b * NOISE_ + threadIdx.x];
    s[threadIdx.x] = v / (1.f + expf(-v));
    __syncthreads();
    int j = jb * 256 + threadIdx.x;
    const float* w = aw + (size_t)j * NOISE_;
    float acc = ab[j];
#pragma unroll 8
    for (int i = 0; i < NOISE_; i++) acc += w[i] * s[i];
    g_params[b * SIXC + j] = acc;
}

// ---------------------------------------------------------------------------
// LN + modulate -> bf16
// ---------------------------------------------------------------------------
__global__ __launch_bounds__(256) void ln_mod_kernel(
    const float* __restrict__ x, int shiftOff, int scaleOff,
    uint32_t* __restrict__ out)
{
    int warp = threadIdx.x >> 5, lane = threadIdx.x & 31;
    int tok = blockIdx.x * 8 + warp;
    int b = tok >> 14;
    const float4* xr = (const float4*)(x + (size_t)tok * C_);
    float4 v[3];
    float s = 0.f;
#pragma unroll
    for (int i = 0; i < 3; i++) {
        v[i] = xr[lane + 32 * i];
        s += v[i].x + v[i].y + v[i].z + v[i].w;
    }
#pragma unroll
    for (int o = 16; o; o >>= 1) s += __shfl_xor_sync(0xffffffffu, s, o);
    float mean = s * (1.f / 384.f);
    float sq = 0.f;
#pragma unroll
    for (int i = 0; i < 3; i++) {
        float dx = v[i].x - mean, dy = v[i].y - mean;
        float dz = v[i].z - mean, dw = v[i].w - mean;
        sq += dx * dx + dy * dy + dz * dz + dw * dw;
    }
#pragma unroll
    for (int o = 16; o; o >>= 1) sq += __shfl_xor_sync(0xffffffffu, sq, o);
    float rstd = rsqrtf(sq * (1.f / 384.f) + EPS_);
    const float4* sh4 = (const float4*)(g_params + b * SIXC + shiftOff);
    const float4* sc4 = (const float4*)(g_params + b * SIXC + scaleOff);
    uint2* orow = (uint2*)(out + (size_t)tok * (C_ / 2));
#pragma unroll
    for (int i = 0; i < 3; i++) {
        int idx = lane + 32 * i;
        float4 s4 = sh4[idx], m4 = sc4[idx];
        float y0 = (v[i].x - mean) * rstd * (1.f + m4.x) + s4.x;
        float y1 = (v[i].y - mean) * rstd * (1.f + m4.y) + s4.y;
        float y2 = (v[i].z - mean) * rstd * (1.f + m4.z) + s4.z;
        float y3 = (v[i].w - mean) * rstd * (1.f + m4.w) + s4.w;
        orow[idx] = make_uint2(packbf(y0, y1), packbf(y2, y3));
    }
}

// ---------------------------------------------------------------------------
// bf16 GEMM (round-9 config, unchanged)
// ---------------------------------------------------------------------------
#define TILE_B   (128 * 128)
#define GEMM_SMEM (3 * 2 * TILE_B)

template <int MODE>
__global__ __launch_bounds__(256, 2) void gemm_bf(
    const __nv_bfloat16* __restrict__ A, const __nv_bfloat16* __restrict__ Bw,
    const float* __restrict__ bias, void* __restrict__ Cout,
    int M, int N, int K,
    const float* __restrict__ res, int gateOff)
{
    extern __shared__ uint8_t smraw[];
    uint32_t sbase = (uint32_t)__cvta_generic_to_shared(smraw);

    int tid  = threadIdx.x;
    int warp = tid >> 5, lane = tid & 31;
    int g = lane >> 2, c = lane & 3;
    int wm = (warp & 1) * 64;
    int wn = (warp >> 1) * 32;
    int bm = blockIdx.y * 128;
    int bn = blockIdx.x * 128;

    int a_row = (lane & 15);
    int a_kb  = (lane >> 4) * 16;
    int b_row = (lane & 7) + ((lane >> 4) & 1) * 8;
    int b_kb  = ((lane >> 3) & 1) * 16;

    float acc[4][4][4];
#pragma unroll
    for (int i = 0; i < 4; i++)
#pragma unroll
        for (int j = 0; j < 4; j++)
#pragma unroll
            for (int t = 0; t < 4; t++) acc[i][j][t] = 0.f;

    int nk = K >> 6;

#define STAGE_LOAD(S, KT)                                                     \
    do {                                                                      \
        if ((KT) < nk) {                                                      \
            int k0 = (KT) << 6;                                               \
            uint32_t abase_ = sbase + (S) * 2 * TILE_B;                       \
            uint32_t bbase_ = abase_ + TILE_B;                                \
            _Pragma("unroll")                                                 \
            for (int i_ = 0; i_ < 4; i_++) {                                  \
                int ch_ = tid + 256 * i_;                                     \
                int row_ = ch_ >> 3, c16_ = (ch_ & 7) << 4;                   \
                uint32_t sw_ = SWZB(row_ * 128 + c16_);                       \
                cp16b(abase_ + sw_,                                           \
                      (const uint8_t*)(A + (size_t)(bm + row_) * K + k0) + c16_); \
                cp16b(bbase_ + sw_,                                           \
                      (const uint8_t*)(Bw + (size_t)(bn + row_) * K + k0) + c16_); \
            }                                                                 \
        }                                                                     \
        asm volatile("cp.async.commit_group;");                               \
    } while (0)

#define COMPUTE(S)                                                            \
    do {                                                                      \
        uint32_t abase_ = sbase + (S) * 2 * TILE_B;                           \
        uint32_t bbase_ = abase_ + TILE_B;                                    \
        _Pragma("unroll")                                                     \
        for (int kk_ = 0; kk_ < 4; kk_++) {                                   \
            int kb_ = kk_ << 5;                                               \
            uint32_t af_[4][4];                                               \
            _Pragma("unroll")                                                 \
            for (int mt_ = 0; mt_ < 4; mt_++)                                 \
                ldsm4b(af_[mt_], abase_ +                                     \
                    SWZB((wm + mt_ * 16 + a_row) * 128 + kb_ + a_kb));        \
            uint32_t bf_[2][4];                                               \
            _Pragma("unroll")                                                 \
            for (int p_ = 0; p_ < 2; p_++)                                    \
                ldsm4b(bf_[p_], bbase_ +                                      \
                    SWZB((wn + p_ * 16 + b_row) * 128 + kb_ + b_kb));         \
            _Pragma("unroll")                                                 \
            for (int mt_ = 0; mt_ < 4; mt_++)                                 \
                _Pragma("unroll")                                             \
                for (int nt_ = 0; nt_ < 4; nt_++)                             \
                    mmabf(acc[mt_][nt_], af_[mt_], &bf_[nt_ >> 1][(nt_ & 1) * 2]); \
        }                                                                     \
    } while (0)

    STAGE_LOAD(0, 0);
    STAGE_LOAD(1, 1);

    for (int kt = 0; kt < nk; kt += 3) {
        asm volatile("cp.async.wait_group 1;");
        __syncthreads();
        STAGE_LOAD(2, kt + 2);
        COMPUTE(0);

        asm volatile("cp.async.wait_group 1;");
        __syncthreads();
        STAGE_LOAD(0, kt + 3);
        COMPUTE(1);

        asm volatile("cp.async.wait_group 1;");
        __syncthreads();
        STAGE_LOAD(1, kt + 4);
        COMPUTE(2);
    }
#undef STAGE_LOAD
#undef COMPUTE

#pragma unroll
    for (int mt = 0; mt < 4; mt++) {
        int r0 = bm + wm + mt * 16 + g;
#pragma unroll
        for (int nt = 0; nt < 4; nt++) {
            int col = bn + wn + nt * 8 + (c << 1);
            float b0 = bias[col], b1 = bias[col + 1];
#pragma unroll
            for (int half = 0; half < 2; half++) {
                int row = r0 + half * 8;
                float v0 = acc[mt][nt][half * 2 + 0] + b0;
                float v1 = acc[mt][nt][half * 2 + 1] + b1;
                if (MODE == 1) {
                    v0 = 0.5f * v0 * (1.f + erff(v0 * 0.7071067811865476f));
                    v1 = 0.5f * v1 * (1.f + erff(v1 * 0.7071067811865476f));
                }
                if (MODE == 2) {
                    int bb = row >> 14;
                    float g0 = g_params[bb * SIXC + gateOff + col];
                    float g1 = g_params[bb * SIXC + gateOff + col + 1];
                    const float2 rr = *(const float2*)(res + (size_t)row * N + col);
                    *(float2*)((float*)Cout + (size_t)row * N + col) =
                        make_float2(rr.x + g0 * v0, rr.y + g1 * v1);
                } else {
                    ((uint32_t*)Cout)[(size_t)row * (N >> 1) + (col >> 1)] = packbf(v0, v1);
                }
            }
        }
    }
}

// ---------------------------------------------------------------------------
// Windowed attention, ldmatrix + cp.async staging. Block = (window, head),
// 128 threads = 4 warps.
// ---------------------------------------------------------------------------
__global__ __launch_bounds__(128) void attn_kernel(
    const uint32_t* __restrict__ qkv, uint32_t* __restrict__ attn_out)
{
    __shared__ uint32_t Qs[64 * 20];
    __shared__ uint32_t Ks[64 * 20];
    __shared__ uint32_t Vs[64 * 20];

    int tid = threadIdx.x;
    int warp = tid >> 5, lane = tid & 31;
    int g = lane >> 2, c = lane & 3;
    int win  = blockIdx.x / HEADS_;
    int head = blockIdx.x % HEADS_;

    int b = win >> 8, rem = win & 255;
    int hb = rem >> 5, rem2 = rem & 31, wb = rem2 >> 2, db = rem2 & 3;
    int base = b * 16384 + hb * 4 * 512 + wb * 4 * 16 + db * 4;

    uint32_t qb = (uint32_t)__cvta_generic_to_shared(Qs);
    uint32_t kb_a = (uint32_t)__cvta_generic_to_shared(Ks);
    uint32_t vb = (uint32_t)__cvta_generic_to_shared(Vs);

    // cp.async staging: row = 4 x 16B chunks; 2 passes of 32 rows each.
    {
        int ch = tid & 3;                 // chunk within row (16B units)
        int rr = tid >> 2;                // rows 0..31
#pragma unroll
        for (int pass = 0; pass < 2; pass++) {
            int r = rr + pass * 32;
            int tok = base + (r >> 4) * 512 + ((r >> 2) & 3) * 16 + (r & 3);
            const uint32_t* p = qkv + (size_t)tok * 576 + head * 16 + ch * 4;
            uint32_t so = (r * 20 + ch * 4) * 4;
            cp16b(qb + so,   p);
            cp16b(kb_a + so, p + 192);
            cp16b(vb + so,   p + 384);
        }
    }
    asm volatile("cp.async.commit_group;");
    asm volatile("cp.async.wait_group 0;");
    __syncthreads();

    int r0 = warp * 16;
    int a_row = lane & 15;
    int a_ko  = (lane >> 4) * 4;
    int b_row = (lane & 7) + ((lane >> 4) & 1) * 8;
    int b_ko  = ((lane >> 3) & 1) * 4;
    int v_row = ((lane >> 3) & 1) * 8 + (lane & 7);
    int v_co  = (lane >> 4) * 4;

    // S = Q @ K^T
    float sacc[8][4];
#pragma unroll
    for (int i = 0; i < 8; i++)
#pragma unroll
        for (int t = 0; t < 4; t++) sacc[i][t] = 0.f;

#pragma unroll
    for (int ks = 0; ks < 2; ks++) {
        int kbo = ks << 3;
        uint32_t af[4];
        ldsm4b(af, qb + ((r0 + a_row) * 20 + kbo + a_ko) * 4);
#pragma unroll
        for (int p = 0; p < 4; p++) {
            uint32_t bfr[4];
            ldsm4b(bfr, kb_a + ((p * 16 + b_row) * 20 + kbo + b_ko) * 4);
            mmabf(sacc[p * 2],     af, &bfr[0]);
            mmabf(sacc[p * 2 + 1], af, &bfr[2]);
        }
    }

    // softmax (no max-pass; scores O(1))
    const float SC2 = 0.17677669529663687f * 1.4426950408889634f;
    float slo = 0.f, shi = 0.f;
#pragma unroll
    for (int nt = 0; nt < 8; nt++) {
        sacc[nt][0] = exp2f(sacc[nt][0] * SC2);
        sacc[nt][1] = exp2f(sacc[nt][1] * SC2);
        sacc[nt][2] = exp2f(sacc[nt][2] * SC2);
        sacc[nt][3] = exp2f(sacc[nt][3] * SC2);
        slo += sacc[nt][0] + sacc[nt][1];
        shi += sacc[nt][2] + sacc[nt][3];
    }
    slo += __shfl_xor_sync(0xffffffffu, slo, 1);
    slo += __shfl_xor_sync(0xffffffffu, slo, 2);
    shi += __shfl_xor_sync(0xffffffffu, shi, 1);
    shi += __shfl_xor_sync(0xffffffffu, shi, 2);

    // O = P @ V
    float o[4][4];
#pragma unroll
    for (int i = 0; i < 4; i++)
#pragma unroll
        for (int t = 0; t < 4; t++) o[i][t] = 0.f;

#pragma unroll
    for (int kt = 0; kt < 4; kt++) {
        uint32_t pa[4];
        pa[0] = packbf(sacc[2 * kt][0],     sacc[2 * kt][1]);
        pa[1] = packbf(sacc[2 * kt][2],     sacc[2 * kt][3]);
        pa[2] = packbf(sacc[2 * kt + 1][0], sacc[2 * kt + 1][1]);
        pa[3] = packbf(sacc[2 * kt + 1][2], sacc[2 * kt + 1][3]);
#pragma unroll
        for (int vt = 0; vt < 2; vt++) {
            uint32_t vf[4];
            ldsm4t(vf, vb + ((kt * 16 + v_row) * 20 + vt * 8 + v_co) * 4);
            mmabf(o[vt * 2],     pa, &vf[0]);
            mmabf(o[vt * 2 + 1], pa, &vf[2]);
        }
    }

    float inv_lo = 1.f / slo, inv_hi = 1.f / shi;
#pragma unroll
    for (int half = 0; half < 2; half++) {
        int r = r0 + g + half * 8;
        int tok = base + (r >> 4) * 512 + ((r >> 2) & 3) * 16 + (r & 3);
        uint32_t* op = attn_out + (size_t)tok * 192 + head * 16;
        float inv = half ? inv_hi : inv_lo;
#pragma unroll
        for (int nt = 0; nt < 4; nt++)
            op[nt * 4 + c] = packbf(o[nt][half * 2] * inv, o[nt][half * 2 + 1] * inv);
    }
}

// ---------------------------------------------------------------------------
// launch
// ---------------------------------------------------------------------------
extern "C" void kernel_launch(void* const* d_in, const int* in_sizes, int n_in,
                              void* d_out, int out_size)
{
    const float* x      = (const float*)d_in[0];
    const float* xn     = (const float*)d_in[1];
    const float* ada_w  = (const float*)d_in[2];
    const float* ada_b  = (const float*)d_in[3];
    const float* qkv_w  = (const float*)d_in[4];
    const float* qkv_b  = (const float*)d_in[5];
    const float* out_w  = (const float*)d_in[6];
    const float* out_b  = (const float*)d_in[7];
    const float* mlp_w1 = (const float*)d_in[8];
    const float* mlp_b1 = (const float*)d_in[9];
    const float* mlp_w2 = (const float*)d_in[10];
    const float* mlp_b2 = (const float*)d_in[11];
    float* out = (float*)d_out;

    void *p_xmod, *p_qkv, *p_attn, *p_x1, *p_h, *p_wq, *p_wo, *p_w1, *p_w2;
    cudaGetSymbolAddress(&p_xmod, g_xmod);
    cudaGetSymbolAddress(&p_qkv,  g_qkv);
    cudaGetSymbolAddress(&p_attn, g_attn);
    cudaGetSymbolAddress(&p_x1,   g_x1);
    cudaGetSymbolAddress(&p_h,    g_h);
    cudaGetSymbolAddress(&p_wq,   g_wq);
    cudaGetSymbolAddress(&p_wo,   g_wo);
    cudaGetSymbolAddress(&p_w1,   g_w1);
    cudaGetSymbolAddress(&p_w2,   g_w2);

    cudaFuncSetAttribute(gemm_bf<0>, cudaFuncAttributeMaxDynamicSharedMemorySize, GEMM_SMEM);
    cudaFuncSetAttribute(gemm_bf<1>, cudaFuncAttributeMaxDynamicSharedMemorySize, GEMM_SMEM);
    cudaFuncSetAttribute(gemm_bf<2>, cudaFuncAttributeMaxDynamicSharedMemorySize, GEMM_SMEM);

    cvt_ada_kernel<<<NCVT + 18, 256>>>(qkv_w, out_w, mlp_w1, mlp_w2,
                                       xn, ada_w, ada_b);

    ln_mod_kernel<<<TOK / 8, 256>>>(x, 0, C_, (uint32_t*)p_xmod);

    {   // QKV -> bf16 (nk=6)
        dim3 grid((3 * C_) / 128, TOK / 128);
        gemm_bf<0><<<grid, 256, GEMM_SMEM>>>(
            (const __nv_bfloat16*)p_xmod, (const __nv_bfloat16*)p_wq,
            qkv_b, p_qkv, TOK, 3 * C_, C_, nullptr, 0);
    }

    attn_kernel<<<NWIN * HEADS_, 128>>>((const uint32_t*)p_qkv, (uint32_t*)p_attn);

    {   // out proj + gate1 + residual -> fp32 (nk=6)
        dim3 grid(C_ / 128, TOK / 128);
        gemm_bf<2><<<grid, 256, GEMM_SMEM>>>(
            (const __nv_bfloat16*)p_attn, (const __nv_bfloat16*)p_wo,
            out_b, p_x1, TOK, C_, C_, x, 2 * C_);
    }

    ln_mod_kernel<<<TOK / 8, 256>>>((const float*)p_x1, 3 * C_, 4 * C_, (uint32_t*)p_xmod);

    {   // MLP1 + GELU -> bf16 (nk=6)
        dim3 grid((4 * C_) / 128, TOK / 128);
        gemm_bf<1><<<grid, 256, GEMM_SMEM>>>(
            (const __nv_bfloat16*)p_xmod, (const __nv_bfloat16*)p_w1,
            mlp_b1, p_h, TOK, 4 * C_, C_, nullptr, 0);
    }

    {   // MLP2 + gate2 + residual -> fp32 (nk=24)
        dim3 grid(C_ / 128, TOK / 128);
        gemm_bf<2><<<grid, 256, GEMM_SMEM>>>(
            (const __nv_bfloat16*)p_h, (const __nv_bfloat16*)p_w2,
            mlp_b2, out, TOK, C_, 4 * C_, (const float*)p_x1, 5 * C_);
    }
}

// round 15
// speedup vs baseline: 1.0910x; 1.0033x over previous
#include <cuda_runtime.h>
#include <cuda_bf16.h>
#include <math.h>
#include <stdint.h>

// ---------------------------------------------------------------------------
// Swin3D ViT block. bf16 mma.sync GEMMs (round-9 config) + ldmatrix attention
// with cp.async staging and smem-restaged coalesced output stores.
// ---------------------------------------------------------------------------

#define TOK      32768
#define C_       384
#define SIXC     2304
#define NOISE_   256
#define HEADS_   12
#define NWIN     512
#define EPS_     1e-5f

// scratch
__device__ float g_params[2 * SIXC];
__device__ float g_x1[TOK * C_];
__device__ __nv_bfloat16 g_xmod[TOK * C_];
__device__ __nv_bfloat16 g_qkv[TOK * 3 * C_];
__device__ __nv_bfloat16 g_attn[TOK * C_];
__device__ __nv_bfloat16 g_h[TOK * 4 * C_];
__device__ __nv_bfloat16 g_wq[3 * C_ * C_];
__device__ __nv_bfloat16 g_wo[C_ * C_];
__device__ __nv_bfloat16 g_w1[4 * C_ * C_];
__device__ __nv_bfloat16 g_w2[4 * C_ * C_];

// ---------------------------------------------------------------------------
__device__ __forceinline__ uint32_t packbf(float lo, float hi) {
    __nv_bfloat162 t = __floats2bfloat162_rn(lo, hi);
    return *(uint32_t*)&t;
}

__device__ __forceinline__ void mmabf(float* d, const uint32_t* a, const uint32_t* b) {
    asm volatile(
        "mma.sync.aligned.m16n8k16.row.col.f32.bf16.bf16.f32 "
        "{%0,%1,%2,%3}, {%4,%5,%6,%7}, {%8,%9}, {%0,%1,%2,%3};"
        : "+f"(d[0]), "+f"(d[1]), "+f"(d[2]), "+f"(d[3])
        : "r"(a[0]), "r"(a[1]), "r"(a[2]), "r"(a[3]), "r"(b[0]), "r"(b[1]));
}

__device__ __forceinline__ void ldsm4b(uint32_t* r, uint32_t saddr) {
    asm volatile("ldmatrix.sync.aligned.m8n8.x4.shared.b16 {%0,%1,%2,%3}, [%4];"
                 : "=r"(r[0]), "=r"(r[1]), "=r"(r[2]), "=r"(r[3]) : "r"(saddr));
}

__device__ __forceinline__ void ldsm4t(uint32_t* r, uint32_t saddr) {
    asm volatile("ldmatrix.sync.aligned.m8n8.x4.trans.shared.b16 {%0,%1,%2,%3}, [%4];"
                 : "=r"(r[0]), "=r"(r[1]), "=r"(r[2]), "=r"(r[3]) : "r"(saddr));
}

__device__ __forceinline__ void cp16b(uint32_t saddr, const void* gptr) {
    asm volatile("cp.async.cg.shared.global [%0], [%1], 16;" :: "r"(saddr), "l"(gptr));
}

#define SWZB(off) ((off) ^ (((off) >> 3) & 0x70))

// ---------------------------------------------------------------------------
// merged: weight conversion + AdaLN param GEMM
// ---------------------------------------------------------------------------
#define NWQ (3 * C_ * C_)
#define NWO (C_ * C_)
#define NW1 (4 * C_ * C_)
#define NW2 (4 * C_ * C_)
#define NCVT ((NWQ + NWO + NW1 + NW2) / 256)

__global__ __launch_bounds__(256) void cvt_ada_kernel(
    const float* __restrict__ wq, const float* __restrict__ wo,
    const float* __restrict__ w1, const float* __restrict__ w2,
    const float* __restrict__ xn, const float* __restrict__ aw,
    const float* __restrict__ ab)
{
    if (blockIdx.x < NCVT) {
        int i = blockIdx.x * 256 + threadIdx.x;
        if (i < NWQ) { g_wq[i] = __float2bfloat16(wq[i]); return; }
        i -= NWQ;
        if (i < NWO) { g_wo[i] = __float2bfloat16(wo[i]); return; }
        i -= NWO;
        if (i < NW1) { g_w1[i] = __float2bfloat16(w1[i]); return; }
        i -= NW1;
        g_w2[i] = __float2bfloat16(w2[i]);
        return;
    }
    __shared__ float s[NOISE_];
    int bid = blockIdx.x - NCVT;
    int b  = bid / 9;
    int jb = bid % 9;
    float v = xn[b * NOISE_ + threadIdx.x];
    s[threadIdx.x] = v / (1.f + expf(-v));
    __syncthreads();
    int j = jb * 256 + threadIdx.x;
    const float* w = aw + (size_t)j * NOISE_;
    float acc = ab[j];
#pragma unroll 8
    for (int i = 0; i < NOISE_; i++) acc += w[i] * s[i];
    g_params[b * SIXC + j] = acc;
}

// ---------------------------------------------------------------------------
// LN + modulate -> bf16
// ---------------------------------------------------------------------------
__global__ __launch_bounds__(256) void ln_mod_kernel(
    const float* __restrict__ x, int shiftOff, int scaleOff,
    uint32_t* __restrict__ out)
{
    int warp = threadIdx.x >> 5, lane = threadIdx.x & 31;
    int tok = blockIdx.x * 8 + warp;
    int b = tok >> 14;
    const float4* xr = (const float4*)(x + (size_t)tok * C_);
    float4 v[3];
    float s = 0.f;
#pragma unroll
    for (int i = 0; i < 3; i++) {
        v[i] = xr[lane + 32 * i];
        s += v[i].x + v[i].y + v[i].z + v[i].w;
    }
#pragma unroll
    for (int o = 16; o; o >>= 1) s += __shfl_xor_sync(0xffffffffu, s, o);
    float mean = s * (1.f / 384.f);
    float sq = 0.f;
#pragma unroll
    for (int i = 0; i < 3; i++) {
        float dx = v[i].x - mean, dy = v[i].y - mean;
        float dz = v[i].z - mean, dw = v[i].w - mean;
        sq += dx * dx + dy * dy + dz * dz + dw * dw;
    }
#pragma unroll
    for (int o = 16; o; o >>= 1) sq += __shfl_xor_sync(0xffffffffu, sq, o);
    float rstd = rsqrtf(sq * (1.f / 384.f) + EPS_);
    const float4* sh4 = (const float4*)(g_params + b * SIXC + shiftOff);
    const float4* sc4 = (const float4*)(g_params + b * SIXC + scaleOff);
    uint2* orow = (uint2*)(out + (size_t)tok * (C_ / 2));
#pragma unroll
    for (int i = 0; i < 3; i++) {
        int idx = lane + 32 * i;
        float4 s4 = sh4[idx], m4 = sc4[idx];
        float y0 = (v[i].x - mean) * rstd * (1.f + m4.x) + s4.x;
        float y1 = (v[i].y - mean) * rstd * (1.f + m4.y) + s4.y;
        float y2 = (v[i].z - mean) * rstd * (1.f + m4.z) + s4.z;
        float y3 = (v[i].w - mean) * rstd * (1.f + m4.w) + s4.w;
        orow[idx] = make_uint2(packbf(y0, y1), packbf(y2, y3));
    }
}

// ---------------------------------------------------------------------------
// bf16 GEMM (round-9 config, unchanged)
// ---------------------------------------------------------------------------
#define TILE_B   (128 * 128)
#define GEMM_SMEM (3 * 2 * TILE_B)

template <int MODE>
__global__ __launch_bounds__(256, 2) void gemm_bf(
    const __nv_bfloat16* __restrict__ A, const __nv_bfloat16* __restrict__ Bw,
    const float* __restrict__ bias, void* __restrict__ Cout,
    int M, int N, int K,
    const float* __restrict__ res, int gateOff)
{
    extern __shared__ uint8_t smraw[];
    uint32_t sbase = (uint32_t)__cvta_generic_to_shared(smraw);

    int tid  = threadIdx.x;
    int warp = tid >> 5, lane = tid & 31;
    int g = lane >> 2, c = lane & 3;
    int wm = (warp & 1) * 64;
    int wn = (warp >> 1) * 32;
    int bm = blockIdx.y * 128;
    int bn = blockIdx.x * 128;

    int a_row = (lane & 15);
    int a_kb  = (lane >> 4) * 16;
    int b_row = (lane & 7) + ((lane >> 4) & 1) * 8;
    int b_kb  = ((lane >> 3) & 1) * 16;

    float acc[4][4][4];
#pragma unroll
    for (int i = 0; i < 4; i++)
#pragma unroll
        for (int j = 0; j < 4; j++)
#pragma unroll
            for (int t = 0; t < 4; t++) acc[i][j][t] = 0.f;

    int nk = K >> 6;

#define STAGE_LOAD(S, KT)                                                     \
    do {                                                                      \
        if ((KT) < nk) {                                                      \
            int k0 = (KT) << 6;                                               \
            uint32_t abase_ = sbase + (S) * 2 * TILE_B;                       \
            uint32_t bbase_ = abase_ + TILE_B;                                \
            _Pragma("unroll")                                                 \
            for (int i_ = 0; i_ < 4; i_++) {                                  \
                int ch_ = tid + 256 * i_;                                     \
                int row_ = ch_ >> 3, c16_ = (ch_ & 7) << 4;                   \
                uint32_t sw_ = SWZB(row_ * 128 + c16_);                       \
                cp16b(abase_ + sw_,                                           \
                      (const uint8_t*)(A + (size_t)(bm + row_) * K + k0) + c16_); \
                cp16b(bbase_ + sw_,                                           \
                      (const uint8_t*)(Bw + (size_t)(bn + row_) * K + k0) + c16_); \
            }                                                                 \
        }                                                                     \
        asm volatile("cp.async.commit_group;");                               \
    } while (0)

#define COMPUTE(S)                                                            \
    do {                                                                      \
        uint32_t abase_ = sbase + (S) * 2 * TILE_B;                           \
        uint32_t bbase_ = abase_ + TILE_B;                                    \
        _Pragma("unroll")                                                     \
        for (int kk_ = 0; kk_ < 4; kk_++) {                                   \
            int kb_ = kk_ << 5;                                               \
            uint32_t af_[4][4];                                               \
            _Pragma("unroll")                                                 \
            for (int mt_ = 0; mt_ < 4; mt_++)                                 \
                ldsm4b(af_[mt_], abase_ +                                     \
                    SWZB((wm + mt_ * 16 + a_row) * 128 + kb_ + a_kb));        \
            uint32_t bf_[2][4];                                               \
            _Pragma("unroll")                                                 \
            for (int p_ = 0; p_ < 2; p_++)                                    \
                ldsm4b(bf_[p_], bbase_ +                                      \
                    SWZB((wn + p_ * 16 + b_row) * 128 + kb_ + b_kb));         \
            _Pragma("unroll")                                                 \
            for (int mt_ = 0; mt_ < 4; mt_++)                                 \
                _Pragma("unroll")                                             \
                for (int nt_ = 0; nt_ < 4; nt_++)                             \
                    mmabf(acc[mt_][nt_], af_[mt_], &bf_[nt_ >> 1][(nt_ & 1) * 2]); \
        }                                                                     \
    } while (0)

    STAGE_LOAD(0, 0);
    STAGE_LOAD(1, 1);

    for (int kt = 0; kt < nk; kt += 3) {
        asm volatile("cp.async.wait_group 1;");
        __syncthreads();
        STAGE_LOAD(2, kt + 2);
        COMPUTE(0);

        asm volatile("cp.async.wait_group 1;");
        __syncthreads();
        STAGE_LOAD(0, kt + 3);
        COMPUTE(1);

        asm volatile("cp.async.wait_group 1;");
        __syncthreads();
        STAGE_LOAD(1, kt + 4);
        COMPUTE(2);
    }
#undef STAGE_LOAD
#undef COMPUTE

#pragma unroll
    for (int mt = 0; mt < 4; mt++) {
        int r0 = bm + wm + mt * 16 + g;
#pragma unroll
        for (int nt = 0; nt < 4; nt++) {
            int col = bn + wn + nt * 8 + (c << 1);
            float b0 = bias[col], b1 = bias[col + 1];
#pragma unroll
            for (int half = 0; half < 2; half++) {
                int row = r0 + half * 8;
                float v0 = acc[mt][nt][half * 2 + 0] + b0;
                float v1 = acc[mt][nt][half * 2 + 1] + b1;
                if (MODE == 1) {
                    v0 = 0.5f * v0 * (1.f + erff(v0 * 0.7071067811865476f));
                    v1 = 0.5f * v1 * (1.f + erff(v1 * 0.7071067811865476f));
                }
                if (MODE == 2) {
                    int bb = row >> 14;
                    float g0 = g_params[bb * SIXC + gateOff + col];
                    float g1 = g_params[bb * SIXC + gateOff + col + 1];
                    const float2 rr = *(const float2*)(res + (size_t)row * N + col);
                    *(float2*)((float*)Cout + (size_t)row * N + col) =
                        make_float2(rr.x + g0 * v0, rr.y + g1 * v1);
                } else {
                    ((uint32_t*)Cout)[(size_t)row * (N >> 1) + (col >> 1)] = packbf(v0, v1);
                }
            }
        }
    }
}

// ---------------------------------------------------------------------------
// Windowed attention, ldmatrix + cp.async staging + coalesced smem-restaged
// output. Block = (window, head), 128 threads = 4 warps.
// ---------------------------------------------------------------------------
__global__ __launch_bounds__(128) void attn_kernel(
    const uint32_t* __restrict__ qkv, uint32_t* __restrict__ attn_out)
{
    __shared__ uint32_t Qs[64 * 20];
    __shared__ uint32_t Ks[64 * 20];
    __shared__ uint32_t Vs[64 * 20];

    int tid = threadIdx.x;
    int warp = tid >> 5, lane = tid & 31;
    int g = lane >> 2, c = lane & 3;
    int win  = blockIdx.x / HEADS_;
    int head = blockIdx.x % HEADS_;

    int b = win >> 8, rem = win & 255;
    int hb = rem >> 5, rem2 = rem & 31, wb = rem2 >> 2, db = rem2 & 3;
    int base = b * 16384 + hb * 4 * 512 + wb * 4 * 16 + db * 4;

    uint32_t qb = (uint32_t)__cvta_generic_to_shared(Qs);
    uint32_t kb_a = (uint32_t)__cvta_generic_to_shared(Ks);
    uint32_t vb = (uint32_t)__cvta_generic_to_shared(Vs);

    // cp.async staging: row = 4 x 16B chunks; 2 passes of 32 rows each.
    {
        int ch = tid & 3;
        int rr = tid >> 2;
#pragma unroll
        for (int pass = 0; pass < 2; pass++) {
            int r = rr + pass * 32;
            int tok = base + (r >> 4) * 512 + ((r >> 2) & 3) * 16 + (r & 3);
            const uint32_t* p = qkv + (size_t)tok * 576 + head * 16 + ch * 4;
            uint32_t so = (r * 20 + ch * 4) * 4;
            cp16b(qb + so,   p);
            cp16b(kb_a + so, p + 192);
            cp16b(vb + so,   p + 384);
        }
    }
    asm volatile("cp.async.commit_group;");
    asm volatile("cp.async.wait_group 0;");
    __syncthreads();

    int r0 = warp * 16;
    int a_row = lane & 15;
    int a_ko  = (lane >> 4) * 4;
    int b_row = (lane & 7) + ((lane >> 4) & 1) * 8;
    int b_ko  = ((lane >> 3) & 1) * 4;
    int v_row = ((lane >> 3) & 1) * 8 + (lane & 7);
    int v_co  = (lane >> 4) * 4;

    // S = Q @ K^T
    float sacc[8][4];
#pragma unroll
    for (int i = 0; i < 8; i++)
#pragma unroll
        for (int t = 0; t < 4; t++) sacc[i][t] = 0.f;

#pragma unroll
    for (int ks = 0; ks < 2; ks++) {
        int kbo = ks << 3;
        uint32_t af[4];
        ldsm4b(af, qb + ((r0 + a_row) * 20 + kbo + a_ko) * 4);
#pragma unroll
        for (int p = 0; p < 4; p++) {
            uint32_t bfr[4];
            ldsm4b(bfr, kb_a + ((p * 16 + b_row) * 20 + kbo + b_ko) * 4);
            mmabf(sacc[p * 2],     af, &bfr[0]);
            mmabf(sacc[p * 2 + 1], af, &bfr[2]);
        }
    }

    // softmax (no max-pass; scores O(1))
    const float SC2 = 0.17677669529663687f * 1.4426950408889634f;
    float slo = 0.f, shi = 0.f;
#pragma unroll
    for (int nt = 0; nt < 8; nt++) {
        sacc[nt][0] = exp2f(sacc[nt][0] * SC2);
        sacc[nt][1] = exp2f(sacc[nt][1] * SC2);
        sacc[nt][2] = exp2f(sacc[nt][2] * SC2);
        sacc[nt][3] = exp2f(sacc[nt][3] * SC2);
        slo += sacc[nt][0] + sacc[nt][1];
        shi += sacc[nt][2] + sacc[nt][3];
    }
    slo += __shfl_xor_sync(0xffffffffu, slo, 1);
    slo += __shfl_xor_sync(0xffffffffu, slo, 2);
    shi += __shfl_xor_sync(0xffffffffu, shi, 1);
    shi += __shfl_xor_sync(0xffffffffu, shi, 2);

    // O = P @ V
    float o[4][4];
#pragma unroll
    for (int i = 0; i < 4; i++)
#pragma unroll
        for (int t = 0; t < 4; t++) o[i][t] = 0.f;

#pragma unroll
    for (int kt = 0; kt < 4; kt++) {
        uint32_t pa[4];
        pa[0] = packbf(sacc[2 * kt][0],     sacc[2 * kt][1]);
        pa[1] = packbf(sacc[2 * kt][2],     sacc[2 * kt][3]);
        pa[2] = packbf(sacc[2 * kt + 1][0], sacc[2 * kt + 1][1]);
        pa[3] = packbf(sacc[2 * kt + 1][2], sacc[2 * kt + 1][3]);
#pragma unroll
        for (int vt = 0; vt < 2; vt++) {
            uint32_t vf[4];
            ldsm4t(vf, vb + ((kt * 16 + v_row) * 20 + vt * 8 + v_co) * 4);
            mmabf(o[vt * 2],     pa, &vf[0]);
            mmabf(o[vt * 2 + 1], pa, &vf[2]);
        }
    }

    // restage outputs in smem (reuse Qs; all smem reads are done), then
    // write coalesced 16B chunks to global.
    float inv_lo = 1.f / slo, inv_hi = 1.f / shi;
    __syncthreads();
#pragma unroll
    for (int half = 0; half < 2; half++) {
        int r = r0 + g + half * 8;
        float inv = half ? inv_hi : inv_lo;
#pragma unroll
        for (int nt = 0; nt < 4; nt++)
            Qs[r * 20 + nt * 4 + c] =
                packbf(o[nt][half * 2] * inv, o[nt][half * 2 + 1] * inv);
    }
    __syncthreads();
    {
        int cc4 = (tid & 3) * 4;
        int rr = tid >> 2;
#pragma unroll
        for (int pass = 0; pass < 2; pass++) {
            int r = rr + pass * 32;
            int tok = base + (r >> 4) * 512 + ((r >> 2) & 3) * 16 + (r & 3);
            uint4 v4 = *(const uint4*)&Qs[r * 20 + cc4];
            *(uint4*)(attn_out + (size_t)tok * 192 + head * 16 + cc4) = v4;
        }
    }
}

// ---------------------------------------------------------------------------
// launch
// ---------------------------------------------------------------------------
extern "C" void kernel_launch(void* const* d_in, const int* in_sizes, int n_in,
                              void* d_out, int out_size)
{
    const float* x      = (const float*)d_in[0];
    const float* xn     = (const float*)d_in[1];
    const float* ada_w  = (const float*)d_in[2];
    const float* ada_b  = (const float*)d_in[3];
    const float* qkv_w  = (const float*)d_in[4];
    const float* qkv_b  = (const float*)d_in[5];
    const float* out_w  = (const float*)d_in[6];
    const float* out_b  = (const float*)d_in[7];
    const float* mlp_w1 = (const float*)d_in[8];
    const float* mlp_b1 = (const float*)d_in[9];
    const float* mlp_w2 = (const float*)d_in[10];
    const float* mlp_b2 = (const float*)d_in[11];
    float* out = (float*)d_out;

    void *p_xmod, *p_qkv, *p_attn, *p_x1, *p_h, *p_wq, *p_wo, *p_w1, *p_w2;
    cudaGetSymbolAddress(&p_xmod, g_xmod);
    cudaGetSymbolAddress(&p_qkv,  g_qkv);
    cudaGetSymbolAddress(&p_attn, g_attn);
    cudaGetSymbolAddress(&p_x1,   g_x1);
    cudaGetSymbolAddress(&p_h,    g_h);
    cudaGetSymbolAddress(&p_wq,   g_wq);
    cudaGetSymbolAddress(&p_wo,   g_wo);
    cudaGetSymbolAddress(&p_w1,   g_w1);
    cudaGetSymbolAddress(&p_w2,   g_w2);

    cudaFuncSetAttribute(gemm_bf<0>, cudaFuncAttributeMaxDynamicSharedMemorySize, GEMM_SMEM);
    cudaFuncSetAttribute(gemm_bf<1>, cudaFuncAttributeMaxDynamicSharedMemorySize, GEMM_SMEM);
    cudaFuncSetAttribute(gemm_bf<2>, cudaFuncAttributeMaxDynamicSharedMemorySize, GEMM_SMEM);

    cvt_ada_kernel<<<NCVT + 18, 256>>>(qkv_w, out_w, mlp_w1, mlp_w2,
                                       xn, ada_w, ada_b);

    ln_mod_kernel<<<TOK / 8, 256>>>(x, 0, C_, (uint32_t*)p_xmod);

    {   // QKV -> bf16 (nk=6)
        dim3 grid((3 * C_) / 128, TOK / 128);
        gemm_bf<0><<<grid, 256, GEMM_SMEM>>>(
            (const __nv_bfloat16*)p_xmod, (const __nv_bfloat16*)p_wq,
            qkv_b, p_qkv, TOK, 3 * C_, C_, nullptr, 0);
    }

    attn_kernel<<<NWIN * HEADS_, 128>>>((const uint32_t*)p_qkv, (uint32_t*)p_attn);

    {   // out proj + gate1 + residual -> fp32 (nk=6)
        dim3 grid(C_ / 128, TOK / 128);
        gemm_bf<2><<<grid, 256, GEMM_SMEM>>>(
            (const __nv_bfloat16*)p_attn, (const __nv_bfloat16*)p_wo,
            out_b, p_x1, TOK, C_, C_, x, 2 * C_);
    }

    ln_mod_kernel<<<TOK / 8, 256>>>((const float*)p_x1, 3 * C_, 4 * C_, (uint32_t*)p_xmod);

    {   // MLP1 + GELU -> bf16 (nk=6)
        dim3 grid((4 * C_) / 128, TOK / 128);
        gemm_bf<1><<<grid, 256, GEMM_SMEM>>>(
            (const __nv_bfloat16*)p_xmod, (const __nv_bfloat16*)p_w1,
            mlp_b1, p_h, TOK, 4 * C_, C_, nullptr, 0);
    }

    {   // MLP2 + gate2 + residual -> fp32 (nk=24)
        dim3 grid(C_ / 128, TOK / 128);
        gemm_bf<2><<<grid, 256, GEMM_SMEM>>>(
            (const __nv_bfloat16*)p_h, (const __nv_bfloat16*)p_w2,
            mlp_b2, out, TOK, C_, 4 * C_, (const float*)p_x1, 5 * C_);
    }
}